// round 6
// baseline (speedup 1.0000x reference)
#include <cuda_runtime.h>
#include <math.h>

#define NN 32768
#define EE 262144
#define FF 64
#define PSC 9
#define ZZ 10
#define NF (NN*FF)
#define HS 68   // padded h row stride (floats)
#define BPZ 30  // blocks per species in node_pre

typedef unsigned long long u64;

// ---------------- device scratch ----------------
__device__ float g_skip_s[NF];
__device__ float g_skip_v[3*NF];
__device__ float g_sup[NF];
__device__ float g_vup[3*NF];
__device__ float g_agg_s[NF];
__device__ float g_agg_v[3*NF];
__device__ float g_w[(size_t)EE*320];   // per-edge TP path weights [E,5,64]
__device__ int g_off[ZZ+1];
__device__ int g_cur[ZZ];
__device__ int g_cnt[ZZ];
__device__ int g_list[NN];

// ---------------- f32x2 packed-math helpers ----------------
__device__ __forceinline__ u64 pack2(float x) {
    u64 r; asm("mov.b64 %0, {%1, %1};" : "=l"(r) : "f"(x)); return r;
}
__device__ __forceinline__ u64 fma2(u64 a, u64 b, u64 c) {
    u64 d; asm("fma.rn.f32x2 %0, %1, %2, %3;" : "=l"(d) : "l"(a), "l"(b), "l"(c)); return d;
}
__device__ __forceinline__ float2 unpk(u64 a) {
    float2 f; asm("mov.b64 {%0, %1}, %2;" : "=f"(f.x), "=f"(f.y) : "l"(a)); return f;
}
__device__ __forceinline__ float silu(float x) { return x / (1.f + __expf(-x)); }

// ---------------- setup kernels ----------------
__global__ void zero_agg() {
    int stride = gridDim.x * blockDim.x;
    int t = blockIdx.x * blockDim.x + threadIdx.x;
    float4 z4 = make_float4(0.f, 0.f, 0.f, 0.f);
    float4* a = (float4*)g_agg_s;
    float4* b = (float4*)g_agg_v;
    for (int i = t; i < NF/4; i += stride) a[i] = z4;
    for (int i = t; i < 3*NF/4; i += stride) b[i] = z4;
    if (t < ZZ) g_cnt[t] = 0;
}
__global__ void count_species(const int* __restrict__ species) {
    int n = blockIdx.x * 256 + threadIdx.x;
    int lane = threadIdx.x & 31;
    int z = species[n];
    unsigned mask = __match_any_sync(0xFFFFFFFFu, z);
    int leader = __ffs(mask) - 1;
    if (lane == leader) atomicAdd(&g_cnt[z], __popc(mask));
}
__global__ void scan_species() {
    if (threadIdx.x == 0) {
        int a = 0;
        for (int z = 0; z < ZZ; z++) { g_off[z] = a; g_cur[z] = a; a += g_cnt[z]; }
        g_off[ZZ] = a;
    }
}
__global__ void fill_species(const int* __restrict__ species) {
    int n = blockIdx.x * 256 + threadIdx.x;
    int lane = threadIdx.x & 31;
    int z = species[n];
    unsigned mask = __match_any_sync(0xFFFFFFFFu, z);
    int leader = __ffs(mask) - 1;
    int rank = __popc(mask & ((1u << lane) - 1));
    int base = 0;
    if (lane == leader) base = atomicAdd(&g_cur[z], __popc(mask));
    base = __shfl_sync(mask, base, leader);
    g_list[base + rank] = n;
}

// ---------------- kernel A: species-sorted skip linear + linear_up ----------------
#define PRE_SMEM_FLOATS (4*4096 + 4*256)
__global__ void node_pre(const float* __restrict__ nf,
                         const float* __restrict__ Wss,
                         const float* __restrict__ Wsv,
                         const float* __restrict__ Wus,
                         const float* __restrict__ Wuv) {
    extern __shared__ float sm[];
    float* sWss = sm;
    float* sWsv = sm + 4096;
    float* sWus = sm + 8192;
    float* sWuv = sm + 12288;
    float* feat = sm + 16384;
    int z = blockIdx.x / BPZ, b = blockIdx.x % BPZ;
    int tid = threadIdx.x;
    const float* wssz = Wss + z * 4096;
    const float* wsvz = Wsv + z * 4096;
    for (int i = tid; i < 4096; i += 256) {
        sWss[i] = wssz[i]; sWsv[i] = wsvz[i]; sWus[i] = Wus[i]; sWuv[i] = Wuv[i];
    }
    __syncthreads();
    int g = tid & 63, grp = tid >> 6, bar = grp + 1;
    float* s_sh = feat + grp * 256;
    float* v_sh = s_sh + 64;
    int lo = g_off[z], hi = g_off[z+1];
    for (int idx = lo + b*4 + grp; idx < hi; idx += BPZ*4) {
        int n = g_list[idx];
        const float* row = nf + (size_t)n * 256;
        s_sh[g]       = row[g];
        v_sh[g]       = row[64 + g];
        v_sh[64 + g]  = row[128 + g];
        v_sh[128 + g] = row[192 + g];
        asm volatile("bar.sync %0, 64;" :: "r"(bar) : "memory");
        float ks = 0.f, kv0 = 0.f, kv1 = 0.f, kv2 = 0.f;
        float us = 0.f, uv0 = 0.f, uv1 = 0.f, uv2 = 0.f;
        #pragma unroll 8
        for (int f = 0; f < FF; f++) {
            float sv = s_sh[f];
            float a0 = v_sh[f*3], a1 = v_sh[f*3+1], a2 = v_sh[f*3+2];
            float w1 = sWss[f*64 + g];
            float w2 = sWsv[f*64 + g];
            float w3 = sWus[f*64 + g];
            float w4 = sWuv[f*64 + g];
            ks  += sv * w1; kv0 += a0 * w2; kv1 += a1 * w2; kv2 += a2 * w2;
            us  += sv * w3; uv0 += a0 * w4; uv1 += a1 * w4; uv2 += a2 * w4;
        }
        const float invZ = 0.039528471f;   // 1/sqrt(64*10)
        const float inv  = 0.125f;         // 1/sqrt(64)
        g_skip_s[n*64 + g]        = ks  * invZ;
        g_skip_v[0*NF + n*64 + g] = kv0 * invZ;
        g_skip_v[1*NF + n*64 + g] = kv1 * invZ;
        g_skip_v[2*NF + n*64 + g] = kv2 * invZ;
        g_sup[n*64 + g]           = us  * inv;
        g_vup[0*NF + n*64 + g]    = uv0 * inv;
        g_vup[1*NF + n*64 + g]    = uv1 * inv;
        g_vup[2*NF + n*64 + g]    = uv2 * inv;
        asm volatile("bar.sync %0, 64;" :: "r"(bar) : "memory");
    }
}

// ---------------- kernel B1: radial MLP, 512 thr / 256-edge tile, 4e x 8c micro-tile ----------------
#define MLP_SMEM_FLOATS (512 + 4096 + 4096 + 20480 + 2048 + 256*HS)

__device__ __forceinline__ void kstep(const float* __restrict__ hin, int e0, int k,
                                      const float* __restrict__ wrow, u64 acc[4][4]) {
    u64 hp[4];
    #pragma unroll
    for (int ee = 0; ee < 4; ee++) hp[ee] = pack2(hin[(e0+ee)*HS + k]);
    ulonglong2 wa = *(const ulonglong2*)(wrow);
    ulonglong2 wb = *(const ulonglong2*)(wrow + 4);
    #pragma unroll
    for (int ee = 0; ee < 4; ee++) {
        acc[0][ee] = fma2(hp[ee], wa.x, acc[0][ee]);
        acc[1][ee] = fma2(hp[ee], wa.y, acc[1][ee]);
        acc[2][ee] = fma2(hp[ee], wb.x, acc[2][ee]);
        acc[3][ee] = fma2(hp[ee], wb.y, acc[3][ee]);
    }
}

__device__ __forceinline__ void zacc(u64 acc[4][4]) {
    #pragma unroll
    for (int gp = 0; gp < 4; gp++)
        #pragma unroll
        for (int ee = 0; ee < 4; ee++) acc[gp][ee] = 0ull;
}

__device__ __forceinline__ void write_silu(u64 acc[4][4], float* h, int e0, int g0, float scale) {
    #pragma unroll
    for (int ee = 0; ee < 4; ee++) {
        float2 a = unpk(acc[0][ee]), b = unpk(acc[1][ee]);
        float2 c = unpk(acc[2][ee]), d = unpk(acc[3][ee]);
        float4 lo = make_float4(silu(a.x*scale), silu(a.y*scale), silu(b.x*scale), silu(b.y*scale));
        float4 hi = make_float4(silu(c.x*scale), silu(c.y*scale), silu(d.x*scale), silu(d.y*scale));
        *(float4*)(h + (e0+ee)*HS + g0)     = lo;
        *(float4*)(h + (e0+ee)*HS + g0 + 4) = hi;
    }
}

__global__ void __launch_bounds__(512)
mlp_kernel(const float* __restrict__ re,
           const float* __restrict__ W1,
           const float* __restrict__ W2,
           const float* __restrict__ W3,
           const float* __restrict__ W4) {
    extern __shared__ float sm[];
    float* sW1 = sm;
    float* sW2 = sW1 + 512;
    float* sW3 = sW2 + 4096;
    float* sW4 = sW3 + 4096;
    float* sRE = sW4 + 20480;
    float* h   = sRE + 2048;
    int tid = threadIdx.x;
    for (int i = tid; i < 512;   i += 512) sW1[i] = W1[i];
    for (int i = tid; i < 4096;  i += 512) { sW2[i] = W2[i]; sW3[i] = W3[i]; }
    for (int i = tid; i < 20480; i += 512) sW4[i] = W4[i];

    int e_base = blockIdx.x * 256;
    for (int i = tid; i < 2048; i += 512) sRE[i] = re[(size_t)e_base*8 + i];
    __syncthreads();

    int cj = tid & 7, ei = tid >> 3;
    int g0 = cj * 8, e0 = ei * 4;

    u64 acc[4][4];

    // layer 1: K=8
    zacc(acc);
    #pragma unroll
    for (int k = 0; k < 8; k++) {
        u64 hp[4];
        #pragma unroll
        for (int ee = 0; ee < 4; ee++) hp[ee] = pack2(sRE[(e0+ee)*8 + k]);
        ulonglong2 wa = *(const ulonglong2*)(sW1 + k*64 + g0);
        ulonglong2 wb = *(const ulonglong2*)(sW1 + k*64 + g0 + 4);
        #pragma unroll
        for (int ee = 0; ee < 4; ee++) {
            acc[0][ee] = fma2(hp[ee], wa.x, acc[0][ee]);
            acc[1][ee] = fma2(hp[ee], wa.y, acc[1][ee]);
            acc[2][ee] = fma2(hp[ee], wb.x, acc[2][ee]);
            acc[3][ee] = fma2(hp[ee], wb.y, acc[3][ee]);
        }
    }
    write_silu(acc, h, e0, g0, 0.35355339f);   // 1/sqrt(8)
    __syncthreads();

    // layer 2: in-place
    zacc(acc);
    #pragma unroll 4
    for (int k = 0; k < 64; k++) kstep(h, e0, k, sW2 + k*64 + g0, acc);
    __syncthreads();
    write_silu(acc, h, e0, g0, 0.125f);
    __syncthreads();

    // layer 3: in-place
    zacc(acc);
    #pragma unroll 4
    for (int k = 0; k < 64; k++) kstep(h, e0, k, sW3 + k*64 + g0, acc);
    __syncthreads();
    write_silu(acc, h, e0, g0, 0.125f);
    __syncthreads();

    // layer 4: 5 path slices of W4, write g_w
    #pragma unroll
    for (int p = 0; p < 5; p++) {
        zacc(acc);
        #pragma unroll 4
        for (int k = 0; k < 64; k++) kstep(h, e0, k, sW4 + k*320 + p*64 + g0, acc);
        #pragma unroll
        for (int ee = 0; ee < 4; ee++) {
            float2 a = unpk(acc[0][ee]), b = unpk(acc[1][ee]);
            float2 c = unpk(acc[2][ee]), d = unpk(acc[3][ee]);
            float* dst = g_w + (size_t)(e_base + e0 + ee)*320 + p*64 + g0;
            *(float4*)dst       = make_float4(a.x*0.125f, a.y*0.125f, b.x*0.125f, b.y*0.125f);
            *(float4*)(dst + 4) = make_float4(c.x*0.125f, c.y*0.125f, d.x*0.125f, d.y*0.125f);
        }
    }
}

// ---------------- kernel B2: tensor product + scatter ----------------
__global__ void tp_scatter(const float* __restrict__ vectors,
                           const int* __restrict__ senders,
                           const int* __restrict__ receivers) {
    int t = blockIdx.x * 256 + threadIdx.x;
    int e = t >> 6, g = t & 63;
    float vx = __ldg(vectors + e*3), vy = __ldg(vectors + e*3 + 1), vz = __ldg(vectors + e*3 + 2);
    float rn = 1.f / (sqrtf(vx*vx + vy*vy + vz*vz) + 1e-9f);
    float y0 = vx * rn, y1 = vy * rn, y2 = vz * rn;

    const float* wrow = g_w + (size_t)e*320 + g;
    float w0  = wrow[0];
    float w1a = wrow[64];
    float w2a = wrow[128];
    float w3a = wrow[192];
    float w4a = wrow[256];

    int sn = __ldg(senders + e), rc = __ldg(receivers + e);
    float ss = g_sup[sn*64 + g];
    float b0 = g_vup[0*NF + sn*64 + g];
    float b1 = g_vup[1*NF + sn*64 + g];
    float b2 = g_vup[2*NF + sn*64 + g];
    float dot = b0*y0 + b1*y1 + b2*y2;
    float c0 = b1*y2 - b2*y1;
    float c1 = b2*y0 - b0*y2;
    float c2 = b0*y1 - b1*y0;
    const float is2 = 0.70710678f;
    float ms  = (w0*ss + w3a*dot) * 0.25f;
    float mv0 = (w1a*y0 + w2a*b0 + w4a*c0*is2) * 0.25f;
    float mv1 = (w1a*y1 + w2a*b1 + w4a*c1*is2) * 0.25f;
    float mv2 = (w1a*y2 + w2a*b2 + w4a*c2*is2) * 0.25f;
    atomicAdd(&g_agg_s[rc*64 + g], ms);
    atomicAdd(&g_agg_v[0*NF + rc*64 + g], mv0);
    atomicAdd(&g_agg_v[1*NF + rc*64 + g], mv1);
    atomicAdd(&g_agg_v[2*NF + rc*64 + g], mv2);
}

// ---------------- kernel C: linear_down + symmetric contraction + post + skip + readout ----------------
#define POST_SMEM_FLOATS (4*4096 + 4*576)
__global__ void node_post(const float* __restrict__ Wds,
                          const float* __restrict__ Wdv,
                          const float* __restrict__ Wsc,
                          const float* __restrict__ Wps,
                          const float* __restrict__ Wpv,
                          const float* __restrict__ Wout,
                          const int*   __restrict__ species,
                          float* __restrict__ out) {
    extern __shared__ float sm[];
    float* sWds = sm;
    float* sWdv = sm + 4096;
    float* sWps = sm + 8192;
    float* sWpv = sm + 12288;
    float* buf  = sm + 16384;
    int tid = threadIdx.x;
    for (int i = tid; i < 4096; i += 256) {
        sWds[i] = Wds[i]; sWdv[i] = Wdv[i]; sWps[i] = Wps[i]; sWpv[i] = Wpv[i];
    }
    __syncthreads();
    int g = tid & 63, grp = tid >> 6, bar = grp + 1;
    float* ags = buf + grp * 576;
    float* agv = ags + 64;
    float* so  = agv + 192;
    float* vo  = so + 64;
    float* red = vo + 192;
    int group_id = blockIdx.x * 4 + grp;
    int totalGroups = gridDim.x * 4;
    for (int n = group_id; n < NN; n += totalGroups) {
        ags[g]       = g_agg_s[n*64 + g];
        agv[g]       = g_agg_v[0*NF + n*64 + g];
        agv[64 + g]  = g_agg_v[1*NF + n*64 + g];
        agv[128 + g] = g_agg_v[2*NF + n*64 + g];
        asm volatile("bar.sync %0, 64;" :: "r"(bar) : "memory");

        float sd = 0.f, vd0 = 0.f, vd1 = 0.f, vd2 = 0.f;
        #pragma unroll 8
        for (int f = 0; f < 64; f++) {
            float a  = ags[f];
            float a0 = agv[f], a1 = agv[64 + f], a2 = agv[128 + f];
            float w1 = sWds[f*64 + g], w2 = sWdv[f*64 + g];
            sd += a * w1; vd0 += a0 * w2; vd1 += a1 * w2; vd2 += a2 * w2;
        }
        sd *= 0.125f; vd0 *= 0.125f; vd1 *= 0.125f; vd2 *= 0.125f;

        int z = species[n];
        const float* wz = Wsc + z * (PSC*64) + g;
        float q0 = __ldg(wz),       q1 = __ldg(wz + 64),  q2 = __ldg(wz + 128);
        float q3 = __ldg(wz + 192), q4 = __ldg(wz + 256), q5 = __ldg(wz + 320);
        float q6 = __ldg(wz + 384), q7 = __ldg(wz + 448), q8 = __ldg(wz + 512);
        float vn2 = vd0*vd0 + vd1*vd1 + vd2*vd2;
        float s2  = sd * sd;
        float sout = q0*sd + q1*s2 + q2*vn2 + q3*s2*sd + q4*sd*vn2;
        float gv   = q5 + q6*sd + q7*s2 + q8*vn2;
        so[g] = sout;
        vo[g] = gv*vd0; vo[64 + g] = gv*vd1; vo[128 + g] = gv*vd2;
        asm volatile("bar.sync %0, 64;" :: "r"(bar) : "memory");

        float sp = 0.f, vp0 = 0.f, vp1 = 0.f, vp2 = 0.f;
        #pragma unroll 8
        for (int f = 0; f < 64; f++) {
            float a  = so[f];
            float a0 = vo[f], a1 = vo[64 + f], a2 = vo[128 + f];
            float w1 = sWps[f*64 + g], w2 = sWpv[f*64 + g];
            sp += a * w1; vp0 += a0 * w2; vp1 += a1 * w2; vp2 += a2 * w2;
        }
        sp  = sp  * 0.125f + g_skip_s[n*64 + g];
        vp0 = vp0 * 0.125f + g_skip_v[0*NF + n*64 + g];
        vp1 = vp1 * 0.125f + g_skip_v[1*NF + n*64 + g];
        vp2 = vp2 * 0.125f + g_skip_v[2*NF + n*64 + g];

        float* mrow = out + NN + (size_t)n * 256;
        mrow[g] = sp;
        mrow[64 + g*3]     = vp0;
        mrow[64 + g*3 + 1] = vp1;
        mrow[64 + g*3 + 2] = vp2;

        red[g] = sp * __ldg(Wout + g);
        asm volatile("bar.sync %0, 64;" :: "r"(bar) : "memory");
        if (g == 0) {
            float t2 = 0.f;
            #pragma unroll
            for (int i = 0; i < 64; i++) t2 += red[i];
            out[n] = t2 * 0.125f;
        }
        asm volatile("bar.sync %0, 64;" :: "r"(bar) : "memory");
    }
}

// ---------------- launch ----------------
extern "C" void kernel_launch(void* const* d_in, const int* in_sizes, int n_in,
                              void* d_out, int out_size) {
    const float* vectors    = (const float*)d_in[0];
    const float* node_feats = (const float*)d_in[1];
    const float* re         = (const float*)d_in[2];
    const float* Wss        = (const float*)d_in[3];
    const float* Wsv        = (const float*)d_in[4];
    const float* Wus        = (const float*)d_in[5];
    const float* Wuv        = (const float*)d_in[6];
    const float* W1         = (const float*)d_in[7];
    const float* W2         = (const float*)d_in[8];
    const float* W3         = (const float*)d_in[9];
    const float* W4         = (const float*)d_in[10];
    const float* Wds        = (const float*)d_in[11];
    const float* Wdv        = (const float*)d_in[12];
    const float* Wsc        = (const float*)d_in[13];
    const float* Wps        = (const float*)d_in[14];
    const float* Wpv        = (const float*)d_in[15];
    const float* Wout       = (const float*)d_in[16];
    const int*   species    = (const int*)d_in[17];
    const int*   senders    = (const int*)d_in[18];
    const int*   receivers  = (const int*)d_in[19];
    float* out = (float*)d_out;

    const int MLP_SMEM  = MLP_SMEM_FLOATS * 4;    // 195584 B
    const int PRE_SMEM  = PRE_SMEM_FLOATS * 4;    // 69632 B
    const int POST_SMEM = POST_SMEM_FLOATS * 4;   // 74752 B
    cudaFuncSetAttribute(mlp_kernel, cudaFuncAttributeMaxDynamicSharedMemorySize, MLP_SMEM);
    cudaFuncSetAttribute(node_pre,   cudaFuncAttributeMaxDynamicSharedMemorySize, PRE_SMEM);
    cudaFuncSetAttribute(node_post,  cudaFuncAttributeMaxDynamicSharedMemorySize, POST_SMEM);

    zero_agg<<<2048, 256>>>();
    count_species<<<NN/256, 256>>>(species);
    scan_species<<<1, 32>>>();
    fill_species<<<NN/256, 256>>>(species);
    node_pre<<<ZZ*BPZ, 256, PRE_SMEM>>>(node_feats, Wss, Wsv, Wus, Wuv);
    mlp_kernel<<<EE/256, 512, MLP_SMEM>>>(re, W1, W2, W3, W4);
    tp_scatter<<<EE*64/256, 256>>>(vectors, senders, receivers);
    node_post<<<444, 256, POST_SMEM>>>(Wds, Wdv, Wsc, Wps, Wpv, Wout, species, out);
}

// round 7
// speedup vs baseline: 1.3920x; 1.3920x over previous
#include <cuda_runtime.h>
#include <math.h>

#define NN 32768
#define EE 262144
#define FF 64
#define PSC 9
#define NF (NN*FF)
#define HS 68   // padded h row stride (floats)

typedef unsigned long long u64;

// ---------------- device scratch ----------------
__device__ float g_skip_s[NF];
__device__ float g_skip_v[3*NF];
__device__ float g_sup[NF];
__device__ float g_vup[3*NF];
__device__ float g_agg_s[NF];
__device__ float g_agg_v[3*NF];

// ---------------- f32x2 packed-math helpers ----------------
__device__ __forceinline__ u64 pack2(float x) {
    u64 r; asm("mov.b64 %0, {%1, %1};" : "=l"(r) : "f"(x)); return r;
}
__device__ __forceinline__ u64 fma2(u64 a, u64 b, u64 c) {
    u64 d; asm("fma.rn.f32x2 %0, %1, %2, %3;" : "=l"(d) : "l"(a), "l"(b), "l"(c)); return d;
}
__device__ __forceinline__ float2 unpk(u64 a) {
    float2 f; asm("mov.b64 {%0, %1}, %2;" : "=f"(f.x), "=f"(f.y) : "l"(a)); return f;
}
__device__ __forceinline__ float silu(float x) { return x / (1.f + __expf(-x)); }

__global__ void zero_agg() {
    int stride = gridDim.x * blockDim.x;
    int t = blockIdx.x * blockDim.x + threadIdx.x;
    float4 z4 = make_float4(0.f, 0.f, 0.f, 0.f);
    float4* a = (float4*)g_agg_s;
    float4* b = (float4*)g_agg_v;
    for (int i = t; i < NF/4; i += stride) a[i] = z4;
    for (int i = t; i < 3*NF/4; i += stride) b[i] = z4;
}

// ---------------- kernel A: per-species skip linear + linear_up (R5 version) ----------------
__global__ void node_pre(const float* __restrict__ nf,
                         const float* __restrict__ Wss,
                         const float* __restrict__ Wsv,
                         const float* __restrict__ Wus,
                         const float* __restrict__ Wuv,
                         const int*   __restrict__ species) {
    __shared__ float sWus[FF*FF], sWuv[FF*FF];
    __shared__ float s_sh[4][FF];
    __shared__ float v_sh[4][3*FF];   // layout f*3+c
    int tid = threadIdx.x;
    for (int i = tid; i < FF*FF; i += 256) { sWus[i] = Wus[i]; sWuv[i] = Wuv[i]; }
    __syncthreads();
    int g = tid & 63, grp = tid >> 6;
    int bar = grp + 1;
    int group_id = blockIdx.x * 4 + grp;
    int totalGroups = gridDim.x * 4;
    for (int n = group_id; n < NN; n += totalGroups) {
        const float* row = nf + (size_t)n * 256;
        s_sh[grp][g]        = row[g];
        v_sh[grp][g]        = row[64 + g];
        v_sh[grp][64 + g]   = row[128 + g];
        v_sh[grp][128 + g]  = row[192 + g];
        asm volatile("bar.sync %0, 64;" :: "r"(bar) : "memory");
        int z = species[n];
        const float* wssz = Wss + z * 4096;
        const float* wsvz = Wsv + z * 4096;
        float ks = 0.f, kv0 = 0.f, kv1 = 0.f, kv2 = 0.f;
        float us = 0.f, uv0 = 0.f, uv1 = 0.f, uv2 = 0.f;
        #pragma unroll 8
        for (int f = 0; f < FF; f++) {
            float sv = s_sh[grp][f];
            float a0 = v_sh[grp][f*3], a1 = v_sh[grp][f*3+1], a2 = v_sh[grp][f*3+2];
            float w1 = __ldg(wssz + f*64 + g);
            float w2 = __ldg(wsvz + f*64 + g);
            float w3 = sWus[f*64 + g];
            float w4 = sWuv[f*64 + g];
            ks  += sv * w1; kv0 += a0 * w2; kv1 += a1 * w2; kv2 += a2 * w2;
            us  += sv * w3; uv0 += a0 * w4; uv1 += a1 * w4; uv2 += a2 * w4;
        }
        const float invZ = 0.039528471f;   // 1/sqrt(64*10)
        const float inv  = 0.125f;         // 1/sqrt(64)
        g_skip_s[n*64 + g]          = ks  * invZ;
        g_skip_v[0*NF + n*64 + g]   = kv0 * invZ;
        g_skip_v[1*NF + n*64 + g]   = kv1 * invZ;
        g_skip_v[2*NF + n*64 + g]   = kv2 * invZ;
        g_sup[n*64 + g]             = us  * inv;
        g_vup[0*NF + n*64 + g]      = uv0 * inv;
        g_vup[1*NF + n*64 + g]      = uv1 * inv;
        g_vup[2*NF + n*64 + g]      = uv2 * inv;
        asm volatile("bar.sync %0, 64;" :: "r"(bar) : "memory");
    }
}

// ---------------- kernel B: fused radial MLP + TP + scatter ----------------
// 512 thr / 256-edge tile / 4e x 8c micro-tile / in-place h buffer.
// smem floats: W1 512 | W2 4096 | W3 4096 | W4 20480 | RE 2048 | h 17408 | Y 1024 | sn 256 | rc 256
#define MLP_SMEM_FLOATS (512 + 4096 + 4096 + 20480 + 2048 + 256*HS + 1024 + 512)

__device__ __forceinline__ void zacc(u64 acc[4][4]) {
    #pragma unroll
    for (int gp = 0; gp < 4; gp++)
        #pragma unroll
        for (int ee = 0; ee < 4; ee++) acc[gp][ee] = 0ull;
}

__device__ __forceinline__ void kstep(const float* __restrict__ hin, int e0, int k,
                                      const float* __restrict__ wrow, u64 acc[4][4]) {
    u64 hp[4];
    #pragma unroll
    for (int ee = 0; ee < 4; ee++) hp[ee] = pack2(hin[(e0+ee)*HS + k]);
    ulonglong2 wa = *(const ulonglong2*)(wrow);
    ulonglong2 wb = *(const ulonglong2*)(wrow + 4);
    #pragma unroll
    for (int ee = 0; ee < 4; ee++) {
        acc[0][ee] = fma2(hp[ee], wa.x, acc[0][ee]);
        acc[1][ee] = fma2(hp[ee], wa.y, acc[1][ee]);
        acc[2][ee] = fma2(hp[ee], wb.x, acc[2][ee]);
        acc[3][ee] = fma2(hp[ee], wb.y, acc[3][ee]);
    }
}

__device__ __forceinline__ void write_silu(u64 acc[4][4], float* h, int e0, int g0, float scale) {
    #pragma unroll
    for (int ee = 0; ee < 4; ee++) {
        float2 a = unpk(acc[0][ee]), b = unpk(acc[1][ee]);
        float2 c = unpk(acc[2][ee]), d = unpk(acc[3][ee]);
        float4 lo = make_float4(silu(a.x*scale), silu(a.y*scale), silu(b.x*scale), silu(b.y*scale));
        float4 hi = make_float4(silu(c.x*scale), silu(c.y*scale), silu(d.x*scale), silu(d.y*scale));
        *(float4*)(h + (e0+ee)*HS + g0)     = lo;
        *(float4*)(h + (e0+ee)*HS + g0 + 4) = hi;
    }
}

__device__ __forceinline__ void unpack8(u64 a[4][4], int ee, float* o) {
    #pragma unroll
    for (int gp = 0; gp < 4; gp++) {
        float2 t = unpk(a[gp][ee]);
        o[gp*2] = t.x; o[gp*2+1] = t.y;
    }
}

__global__ void __launch_bounds__(512)
mlp_tp_kernel(const float* __restrict__ re,
              const float* __restrict__ vectors,
              const float* __restrict__ W1,
              const float* __restrict__ W2,
              const float* __restrict__ W3,
              const float* __restrict__ W4,
              const int* __restrict__ senders,
              const int* __restrict__ receivers) {
    extern __shared__ float sm[];
    float* sW1 = sm;
    float* sW2 = sW1 + 512;
    float* sW3 = sW2 + 4096;
    float* sW4 = sW3 + 4096;
    float* sRE = sW4 + 20480;
    float* h   = sRE + 2048;
    float* sY  = h + 256*HS;          // [256][4]
    int*   sSn = (int*)(sY + 1024);
    int*   sRc = sSn + 256;
    int tid = threadIdx.x;
    for (int i = tid; i < 512;   i += 512) sW1[i] = W1[i];
    for (int i = tid; i < 4096;  i += 512) { sW2[i] = W2[i]; sW3[i] = W3[i]; }
    for (int i = tid; i < 20480; i += 512) sW4[i] = W4[i];

    int e_base = blockIdx.x * 256;
    for (int i = tid; i < 2048; i += 512) sRE[i] = re[(size_t)e_base*8 + i];
    if (tid < 256) {
        int e = e_base + tid;
        float vx = __ldg(vectors + e*3), vy = __ldg(vectors + e*3 + 1), vz = __ldg(vectors + e*3 + 2);
        float rn = 1.f / (sqrtf(vx*vx + vy*vy + vz*vz) + 1e-9f);
        sY[tid*4]     = vx * rn;
        sY[tid*4 + 1] = vy * rn;
        sY[tid*4 + 2] = vz * rn;
        sSn[tid] = __ldg(senders + e);
        sRc[tid] = __ldg(receivers + e);
    }
    __syncthreads();

    int cj = tid & 7, ei = tid >> 3;
    int g0 = cj * 8, e0 = ei * 4;

    u64 acc[4][4];

    // layer 1: K=8
    zacc(acc);
    #pragma unroll
    for (int k = 0; k < 8; k++) {
        u64 hp[4];
        #pragma unroll
        for (int ee = 0; ee < 4; ee++) hp[ee] = pack2(sRE[(e0+ee)*8 + k]);
        ulonglong2 wa = *(const ulonglong2*)(sW1 + k*64 + g0);
        ulonglong2 wb = *(const ulonglong2*)(sW1 + k*64 + g0 + 4);
        #pragma unroll
        for (int ee = 0; ee < 4; ee++) {
            acc[0][ee] = fma2(hp[ee], wa.x, acc[0][ee]);
            acc[1][ee] = fma2(hp[ee], wa.y, acc[1][ee]);
            acc[2][ee] = fma2(hp[ee], wb.x, acc[2][ee]);
            acc[3][ee] = fma2(hp[ee], wb.y, acc[3][ee]);
        }
    }
    write_silu(acc, h, e0, g0, 0.35355339f);   // 1/sqrt(8)
    __syncthreads();

    // layer 2: in-place
    zacc(acc);
    #pragma unroll 4
    for (int k = 0; k < 64; k++) kstep(h, e0, k, sW2 + k*64 + g0, acc);
    __syncthreads();
    write_silu(acc, h, e0, g0, 0.125f);
    __syncthreads();

    // layer 3: in-place
    zacc(acc);
    #pragma unroll 4
    for (int k = 0; k < 64; k++) kstep(h, e0, k, sW3 + k*64 + g0, acc);
    __syncthreads();
    write_silu(acc, h, e0, g0, 0.125f);
    __syncthreads();                       // h = final hidden (read-only from here)

    const float K1 = 0.03125f;       // 0.125 * EPS(0.25)
    const float K4 = 0.022097087f;   // 0.125 * 0.25 / sqrt(2)

    // ---- stage A: paths 0 & 3 -> scalar scatter ----
    {
        u64 accA[4][4], accB[4][4];
        zacc(accA); zacc(accB);
        #pragma unroll 4
        for (int k = 0; k < 64; k++) {
            kstep(h, e0, k, sW4 + k*320 + 0   + g0, accA);
            kstep(h, e0, k, sW4 + k*320 + 192 + g0, accB);
        }
        #pragma unroll
        for (int ee = 0; ee < 4; ee++) {
            int le = e0 + ee;
            int sn = sSn[le], rc = sRc[le];
            float y0 = sY[le*4], y1 = sY[le*4+1], y2 = sY[le*4+2];
            float4 sl  = *(const float4*)(g_sup + sn*64 + g0);
            float4 sh2 = *(const float4*)(g_sup + sn*64 + g0 + 4);
            float4 v0l = *(const float4*)(g_vup + 0*NF + sn*64 + g0);
            float4 v0h = *(const float4*)(g_vup + 0*NF + sn*64 + g0 + 4);
            float4 v1l = *(const float4*)(g_vup + 1*NF + sn*64 + g0);
            float4 v1h = *(const float4*)(g_vup + 1*NF + sn*64 + g0 + 4);
            float4 v2l = *(const float4*)(g_vup + 2*NF + sn*64 + g0);
            float4 v2h = *(const float4*)(g_vup + 2*NF + sn*64 + g0 + 4);
            float ssv[8] = {sl.x, sl.y, sl.z, sl.w, sh2.x, sh2.y, sh2.z, sh2.w};
            float b0v[8] = {v0l.x, v0l.y, v0l.z, v0l.w, v0h.x, v0h.y, v0h.z, v0h.w};
            float b1v[8] = {v1l.x, v1l.y, v1l.z, v1l.w, v1h.x, v1h.y, v1h.z, v1h.w};
            float b2v[8] = {v2l.x, v2l.y, v2l.z, v2l.w, v2h.x, v2h.y, v2h.z, v2h.w};
            float w0v[8], w3v[8];
            unpack8(accA, ee, w0v);
            unpack8(accB, ee, w3v);
            float* dst = g_agg_s + rc*64 + g0;
            #pragma unroll
            for (int j = 0; j < 8; j++) {
                float dot = b0v[j]*y0 + b1v[j]*y1 + b2v[j]*y2;
                atomicAdd(dst + j, K1 * (w0v[j]*ssv[j] + w3v[j]*dot));
            }
        }
    }

    // ---- stage B: paths 1, 2, 4 -> vector scatter ----
    {
        u64 acc1[4][4], acc2[4][4], acc4[4][4];
        zacc(acc1); zacc(acc2); zacc(acc4);
        #pragma unroll 2
        for (int k = 0; k < 64; k++) {
            kstep(h, e0, k, sW4 + k*320 + 64  + g0, acc1);
            kstep(h, e0, k, sW4 + k*320 + 128 + g0, acc2);
            kstep(h, e0, k, sW4 + k*320 + 256 + g0, acc4);
        }
        #pragma unroll
        for (int ee = 0; ee < 4; ee++) {
            int le = e0 + ee;
            int sn = sSn[le], rc = sRc[le];
            float y0 = sY[le*4], y1 = sY[le*4+1], y2 = sY[le*4+2];
            float4 v0l = *(const float4*)(g_vup + 0*NF + sn*64 + g0);
            float4 v0h = *(const float4*)(g_vup + 0*NF + sn*64 + g0 + 4);
            float4 v1l = *(const float4*)(g_vup + 1*NF + sn*64 + g0);
            float4 v1h = *(const float4*)(g_vup + 1*NF + sn*64 + g0 + 4);
            float4 v2l = *(const float4*)(g_vup + 2*NF + sn*64 + g0);
            float4 v2h = *(const float4*)(g_vup + 2*NF + sn*64 + g0 + 4);
            float b0v[8] = {v0l.x, v0l.y, v0l.z, v0l.w, v0h.x, v0h.y, v0h.z, v0h.w};
            float b1v[8] = {v1l.x, v1l.y, v1l.z, v1l.w, v1h.x, v1h.y, v1h.z, v1h.w};
            float b2v[8] = {v2l.x, v2l.y, v2l.z, v2l.w, v2h.x, v2h.y, v2h.z, v2h.w};
            float w1v[8], w2v[8], w4v[8];
            unpack8(acc1, ee, w1v);
            unpack8(acc2, ee, w2v);
            unpack8(acc4, ee, w4v);
            float* d0 = g_agg_v + 0*NF + rc*64 + g0;
            float* d1 = g_agg_v + 1*NF + rc*64 + g0;
            float* d2 = g_agg_v + 2*NF + rc*64 + g0;
            #pragma unroll
            for (int j = 0; j < 8; j++) {
                float c0 = b1v[j]*y2 - b2v[j]*y1;
                float c1 = b2v[j]*y0 - b0v[j]*y2;
                float c2 = b0v[j]*y1 - b1v[j]*y0;
                atomicAdd(d0 + j, K1*(w1v[j]*y0 + w2v[j]*b0v[j]) + K4*w4v[j]*c0);
                atomicAdd(d1 + j, K1*(w1v[j]*y1 + w2v[j]*b1v[j]) + K4*w4v[j]*c1);
                atomicAdd(d2 + j, K1*(w1v[j]*y2 + w2v[j]*b2v[j]) + K4*w4v[j]*c2);
            }
        }
    }
}

// ---------------- kernel C: linear_down + symmetric contraction + post + skip + readout ----------------
#define POST_SMEM_FLOATS (4*4096 + 4*576)
__global__ void node_post(const float* __restrict__ Wds,
                          const float* __restrict__ Wdv,
                          const float* __restrict__ Wsc,
                          const float* __restrict__ Wps,
                          const float* __restrict__ Wpv,
                          const float* __restrict__ Wout,
                          const int*   __restrict__ species,
                          float* __restrict__ out) {
    extern __shared__ float sm[];
    float* sWds = sm;
    float* sWdv = sm + 4096;
    float* sWps = sm + 8192;
    float* sWpv = sm + 12288;
    float* buf  = sm + 16384;
    int tid = threadIdx.x;
    for (int i = tid; i < 4096; i += 256) {
        sWds[i] = Wds[i]; sWdv[i] = Wdv[i]; sWps[i] = Wps[i]; sWpv[i] = Wpv[i];
    }
    __syncthreads();
    int g = tid & 63, grp = tid >> 6, bar = grp + 1;
    float* ags = buf + grp * 576;
    float* agv = ags + 64;
    float* so  = agv + 192;
    float* vo  = so + 64;
    float* red = vo + 192;
    int group_id = blockIdx.x * 4 + grp;
    int totalGroups = gridDim.x * 4;
    for (int n = group_id; n < NN; n += totalGroups) {
        ags[g]       = g_agg_s[n*64 + g];
        agv[g]       = g_agg_v[0*NF + n*64 + g];
        agv[64 + g]  = g_agg_v[1*NF + n*64 + g];
        agv[128 + g] = g_agg_v[2*NF + n*64 + g];
        asm volatile("bar.sync %0, 64;" :: "r"(bar) : "memory");

        float sd = 0.f, vd0 = 0.f, vd1 = 0.f, vd2 = 0.f;
        #pragma unroll 8
        for (int f = 0; f < 64; f++) {
            float a  = ags[f];
            float a0 = agv[f], a1 = agv[64 + f], a2 = agv[128 + f];
            float w1 = sWds[f*64 + g], w2 = sWdv[f*64 + g];
            sd += a * w1; vd0 += a0 * w2; vd1 += a1 * w2; vd2 += a2 * w2;
        }
        sd *= 0.125f; vd0 *= 0.125f; vd1 *= 0.125f; vd2 *= 0.125f;

        int z = species[n];
        const float* wz = Wsc + z * (PSC*64) + g;
        float q0 = __ldg(wz),       q1 = __ldg(wz + 64),  q2 = __ldg(wz + 128);
        float q3 = __ldg(wz + 192), q4 = __ldg(wz + 256), q5 = __ldg(wz + 320);
        float q6 = __ldg(wz + 384), q7 = __ldg(wz + 448), q8 = __ldg(wz + 512);
        float vn2 = vd0*vd0 + vd1*vd1 + vd2*vd2;
        float s2  = sd * sd;
        float sout = q0*sd + q1*s2 + q2*vn2 + q3*s2*sd + q4*sd*vn2;
        float gv   = q5 + q6*sd + q7*s2 + q8*vn2;
        so[g] = sout;
        vo[g] = gv*vd0; vo[64 + g] = gv*vd1; vo[128 + g] = gv*vd2;
        asm volatile("bar.sync %0, 64;" :: "r"(bar) : "memory");

        float sp = 0.f, vp0 = 0.f, vp1 = 0.f, vp2 = 0.f;
        #pragma unroll 8
        for (int f = 0; f < 64; f++) {
            float a  = so[f];
            float a0 = vo[f], a1 = vo[64 + f], a2 = vo[128 + f];
            float w1 = sWps[f*64 + g], w2 = sWpv[f*64 + g];
            sp += a * w1; vp0 += a0 * w2; vp1 += a1 * w2; vp2 += a2 * w2;
        }
        sp  = sp  * 0.125f + g_skip_s[n*64 + g];
        vp0 = vp0 * 0.125f + g_skip_v[0*NF + n*64 + g];
        vp1 = vp1 * 0.125f + g_skip_v[1*NF + n*64 + g];
        vp2 = vp2 * 0.125f + g_skip_v[2*NF + n*64 + g];

        float* mrow = out + NN + (size_t)n * 256;
        mrow[g] = sp;
        mrow[64 + g*3]     = vp0;
        mrow[64 + g*3 + 1] = vp1;
        mrow[64 + g*3 + 2] = vp2;

        red[g] = sp * __ldg(Wout + g);
        asm volatile("bar.sync %0, 64;" :: "r"(bar) : "memory");
        if (g == 0) {
            float t2 = 0.f;
            #pragma unroll
            for (int i = 0; i < 64; i++) t2 += red[i];
            out[n] = t2 * 0.125f;
        }
        asm volatile("bar.sync %0, 64;" :: "r"(bar) : "memory");
    }
}

// ---------------- launch ----------------
extern "C" void kernel_launch(void* const* d_in, const int* in_sizes, int n_in,
                              void* d_out, int out_size) {
    const float* vectors    = (const float*)d_in[0];
    const float* node_feats = (const float*)d_in[1];
    const float* re         = (const float*)d_in[2];
    const float* Wss        = (const float*)d_in[3];
    const float* Wsv        = (const float*)d_in[4];
    const float* Wus        = (const float*)d_in[5];
    const float* Wuv        = (const float*)d_in[6];
    const float* W1         = (const float*)d_in[7];
    const float* W2         = (const float*)d_in[8];
    const float* W3         = (const float*)d_in[9];
    const float* W4         = (const float*)d_in[10];
    const float* Wds        = (const float*)d_in[11];
    const float* Wdv        = (const float*)d_in[12];
    const float* Wsc        = (const float*)d_in[13];
    const float* Wps        = (const float*)d_in[14];
    const float* Wpv        = (const float*)d_in[15];
    const float* Wout       = (const float*)d_in[16];
    const int*   species    = (const int*)d_in[17];
    const int*   senders    = (const int*)d_in[18];
    const int*   receivers  = (const int*)d_in[19];
    float* out = (float*)d_out;

    const int MLP_SMEM  = MLP_SMEM_FLOATS * 4;    // 201728 B
    const int POST_SMEM = POST_SMEM_FLOATS * 4;   // 74752 B
    cudaFuncSetAttribute(mlp_tp_kernel, cudaFuncAttributeMaxDynamicSharedMemorySize, MLP_SMEM);
    cudaFuncSetAttribute(node_post,     cudaFuncAttributeMaxDynamicSharedMemorySize, POST_SMEM);

    zero_agg<<<2048, 256>>>();
    node_pre<<<592, 256>>>(node_feats, Wss, Wsv, Wus, Wuv, species);
    mlp_tp_kernel<<<EE/256, 512, MLP_SMEM>>>(re, vectors, W1, W2, W3, W4, senders, receivers);
    node_post<<<444, 256, POST_SMEM>>>(Wds, Wdv, Wsc, Wps, Wpv, Wout, species, out);
}

// round 8
// speedup vs baseline: 1.5659x; 1.1249x over previous
#include <cuda_runtime.h>
#include <math.h>

#define NN 32768
#define EE 262144
#define FF 64
#define PSC 9
#define NF (NN*FF)
#define HS 68   // padded h row stride (floats)

typedef unsigned long long u64;

// ---------------- device scratch ----------------
__device__ float g_skip_s[NF];
__device__ float g_skip_v[3*NF];
__device__ float g_sup[NF];
__device__ float g_vup[3*NF];
__device__ float g_agg_s[NF];
__device__ float g_agg_v[3*NF];
__device__ float g_w[(size_t)EE*320];   // per-edge TP path weights [E,5,64]

// ---------------- f32x2 packed-math helpers ----------------
__device__ __forceinline__ u64 pack2(float x) {
    u64 r; asm("mov.b64 %0, {%1, %1};" : "=l"(r) : "f"(x)); return r;
}
__device__ __forceinline__ u64 fma2(u64 a, u64 b, u64 c) {
    u64 d; asm("fma.rn.f32x2 %0, %1, %2, %3;" : "=l"(d) : "l"(a), "l"(b), "l"(c)); return d;
}
__device__ __forceinline__ float2 unpk(u64 a) {
    float2 f; asm("mov.b64 {%0, %1}, %2;" : "=f"(f.x), "=f"(f.y) : "l"(a)); return f;
}
__device__ __forceinline__ float silu(float x) { return x / (1.f + __expf(-x)); }

__global__ void zero_agg() {
    int stride = gridDim.x * blockDim.x;
    int t = blockIdx.x * blockDim.x + threadIdx.x;
    for (int i = t; i < NF; i += stride) g_agg_s[i] = 0.f;
    for (int i = t; i < 3*NF; i += stride) g_agg_v[i] = 0.f;
}

// ---------------- kernel A: per-species skip linear + linear_up (512 thr, 8 groups) ----------------
__global__ void __launch_bounds__(512)
node_pre(const float* __restrict__ nf,
         const float* __restrict__ Wss,
         const float* __restrict__ Wsv,
         const float* __restrict__ Wus,
         const float* __restrict__ Wuv,
         const int*   __restrict__ species) {
    __shared__ float sWus[FF*FF], sWuv[FF*FF];
    __shared__ float s_sh[8][FF];
    __shared__ float v_sh[8][3*FF];   // layout f*3+c
    int tid = threadIdx.x;
    for (int i = tid; i < FF*FF; i += 512) { sWus[i] = Wus[i]; sWuv[i] = Wuv[i]; }
    __syncthreads();
    int g = tid & 63, grp = tid >> 6;
    int bar = grp + 1;
    int group_id = blockIdx.x * 8 + grp;
    int totalGroups = gridDim.x * 8;
    for (int n = group_id; n < NN; n += totalGroups) {
        const float* row = nf + (size_t)n * 256;
        s_sh[grp][g]        = row[g];
        v_sh[grp][g]        = row[64 + g];
        v_sh[grp][64 + g]   = row[128 + g];
        v_sh[grp][128 + g]  = row[192 + g];
        asm volatile("bar.sync %0, 64;" :: "r"(bar) : "memory");
        int z = species[n];
        const float* wssz = Wss + z * 4096;
        const float* wsvz = Wsv + z * 4096;
        float ks = 0.f, kv0 = 0.f, kv1 = 0.f, kv2 = 0.f;
        float us = 0.f, uv0 = 0.f, uv1 = 0.f, uv2 = 0.f;
        #pragma unroll 8
        for (int f = 0; f < FF; f++) {
            float sv = s_sh[grp][f];
            float a0 = v_sh[grp][f*3], a1 = v_sh[grp][f*3+1], a2 = v_sh[grp][f*3+2];
            float w1 = __ldg(wssz + f*64 + g);
            float w2 = __ldg(wsvz + f*64 + g);
            float w3 = sWus[f*64 + g];
            float w4 = sWuv[f*64 + g];
            ks  += sv * w1; kv0 += a0 * w2; kv1 += a1 * w2; kv2 += a2 * w2;
            us  += sv * w3; uv0 += a0 * w4; uv1 += a1 * w4; uv2 += a2 * w4;
        }
        const float invZ = 0.039528471f;   // 1/sqrt(64*10)
        const float inv  = 0.125f;         // 1/sqrt(64)
        g_skip_s[n*64 + g]          = ks  * invZ;
        g_skip_v[0*NF + n*64 + g]   = kv0 * invZ;
        g_skip_v[1*NF + n*64 + g]   = kv1 * invZ;
        g_skip_v[2*NF + n*64 + g]   = kv2 * invZ;
        g_sup[n*64 + g]             = us  * inv;
        g_vup[0*NF + n*64 + g]      = uv0 * inv;
        g_vup[1*NF + n*64 + g]      = uv1 * inv;
        g_vup[2*NF + n*64 + g]      = uv2 * inv;
        asm volatile("bar.sync %0, 64;" :: "r"(bar) : "memory");
    }
}

// ---------------- kernel B1: radial MLP (R5 exact) ----------------
#define MLP_SMEM_FLOATS (512 + 4096 + 4096 + 20480 + 2048 + 256*HS)

__device__ __forceinline__ void kstep(const float* __restrict__ hin, int e0, int k,
                                      const float* __restrict__ wrow, u64 acc[4][4]) {
    u64 hp[4];
    #pragma unroll
    for (int ee = 0; ee < 4; ee++) hp[ee] = pack2(hin[(e0+ee)*HS + k]);
    ulonglong2 wa = *(const ulonglong2*)(wrow);
    ulonglong2 wb = *(const ulonglong2*)(wrow + 4);
    #pragma unroll
    for (int ee = 0; ee < 4; ee++) {
        acc[0][ee] = fma2(hp[ee], wa.x, acc[0][ee]);
        acc[1][ee] = fma2(hp[ee], wa.y, acc[1][ee]);
        acc[2][ee] = fma2(hp[ee], wb.x, acc[2][ee]);
        acc[3][ee] = fma2(hp[ee], wb.y, acc[3][ee]);
    }
}

__device__ __forceinline__ void zacc(u64 acc[4][4]) {
    #pragma unroll
    for (int gp = 0; gp < 4; gp++)
        #pragma unroll
        for (int ee = 0; ee < 4; ee++) acc[gp][ee] = 0ull;
}

__device__ __forceinline__ void write_silu(u64 acc[4][4], float* h, int e0, int g0, float scale) {
    #pragma unroll
    for (int ee = 0; ee < 4; ee++) {
        float2 a = unpk(acc[0][ee]), b = unpk(acc[1][ee]);
        float2 c = unpk(acc[2][ee]), d = unpk(acc[3][ee]);
        float4 lo = make_float4(silu(a.x*scale), silu(a.y*scale), silu(b.x*scale), silu(b.y*scale));
        float4 hi = make_float4(silu(c.x*scale), silu(c.y*scale), silu(d.x*scale), silu(d.y*scale));
        *(float4*)(h + (e0+ee)*HS + g0)     = lo;
        *(float4*)(h + (e0+ee)*HS + g0 + 4) = hi;
    }
}

__global__ void __launch_bounds__(512)
mlp_kernel(const float* __restrict__ re,
           const float* __restrict__ W1,
           const float* __restrict__ W2,
           const float* __restrict__ W3,
           const float* __restrict__ W4) {
    extern __shared__ float sm[];
    float* sW1 = sm;
    float* sW2 = sW1 + 512;
    float* sW3 = sW2 + 4096;
    float* sW4 = sW3 + 4096;
    float* sRE = sW4 + 20480;
    float* h   = sRE + 2048;
    int tid = threadIdx.x;
    for (int i = tid; i < 512;   i += 512) sW1[i] = W1[i];
    for (int i = tid; i < 4096;  i += 512) { sW2[i] = W2[i]; sW3[i] = W3[i]; }
    for (int i = tid; i < 20480; i += 512) sW4[i] = W4[i];

    int e_base = blockIdx.x * 256;
    for (int i = tid; i < 2048; i += 512) sRE[i] = re[(size_t)e_base*8 + i];
    __syncthreads();

    int cj = tid & 7, ei = tid >> 3;
    int g0 = cj * 8, e0 = ei * 4;

    u64 acc[4][4];

    // layer 1: K=8
    zacc(acc);
    #pragma unroll
    for (int k = 0; k < 8; k++) {
        u64 hp[4];
        #pragma unroll
        for (int ee = 0; ee < 4; ee++) hp[ee] = pack2(sRE[(e0+ee)*8 + k]);
        ulonglong2 wa = *(const ulonglong2*)(sW1 + k*64 + g0);
        ulonglong2 wb = *(const ulonglong2*)(sW1 + k*64 + g0 + 4);
        #pragma unroll
        for (int ee = 0; ee < 4; ee++) {
            acc[0][ee] = fma2(hp[ee], wa.x, acc[0][ee]);
            acc[1][ee] = fma2(hp[ee], wa.y, acc[1][ee]);
            acc[2][ee] = fma2(hp[ee], wb.x, acc[2][ee]);
            acc[3][ee] = fma2(hp[ee], wb.y, acc[3][ee]);
        }
    }
    write_silu(acc, h, e0, g0, 0.35355339f);   // 1/sqrt(8)
    __syncthreads();

    // layer 2: in-place
    zacc(acc);
    #pragma unroll 4
    for (int k = 0; k < 64; k++) kstep(h, e0, k, sW2 + k*64 + g0, acc);
    __syncthreads();
    write_silu(acc, h, e0, g0, 0.125f);
    __syncthreads();

    // layer 3: in-place
    zacc(acc);
    #pragma unroll 4
    for (int k = 0; k < 64; k++) kstep(h, e0, k, sW3 + k*64 + g0, acc);
    __syncthreads();
    write_silu(acc, h, e0, g0, 0.125f);
    __syncthreads();

    // layer 4: 5 path slices of W4, write g_w
    #pragma unroll
    for (int p = 0; p < 5; p++) {
        zacc(acc);
        #pragma unroll 4
        for (int k = 0; k < 64; k++) kstep(h, e0, k, sW4 + k*320 + p*64 + g0, acc);
        #pragma unroll
        for (int ee = 0; ee < 4; ee++) {
            float2 a = unpk(acc[0][ee]), b = unpk(acc[1][ee]);
            float2 c = unpk(acc[2][ee]), d = unpk(acc[3][ee]);
            float* dst = g_w + (size_t)(e_base + e0 + ee)*320 + p*64 + g0;
            *(float4*)dst       = make_float4(a.x*0.125f, a.y*0.125f, b.x*0.125f, b.y*0.125f);
            *(float4*)(dst + 4) = make_float4(c.x*0.125f, c.y*0.125f, d.x*0.125f, d.y*0.125f);
        }
    }
}

// ---------------- kernel B2: tensor product + scatter (R5 exact) ----------------
__global__ void tp_scatter(const float* __restrict__ vectors,
                           const int* __restrict__ senders,
                           const int* __restrict__ receivers) {
    int t = blockIdx.x * 256 + threadIdx.x;
    int e = t >> 6, g = t & 63;
    float vx = __ldg(vectors + e*3), vy = __ldg(vectors + e*3 + 1), vz = __ldg(vectors + e*3 + 2);
    float rn = 1.f / (sqrtf(vx*vx + vy*vy + vz*vz) + 1e-9f);
    float y0 = vx * rn, y1 = vy * rn, y2 = vz * rn;

    const float* wrow = g_w + (size_t)e*320 + g;
    float w0  = wrow[0];
    float w1a = wrow[64];
    float w2a = wrow[128];
    float w3a = wrow[192];
    float w4a = wrow[256];

    int sn = __ldg(senders + e), rc = __ldg(receivers + e);
    float ss = g_sup[sn*64 + g];
    float b0 = g_vup[0*NF + sn*64 + g];
    float b1 = g_vup[1*NF + sn*64 + g];
    float b2 = g_vup[2*NF + sn*64 + g];
    float dot = b0*y0 + b1*y1 + b2*y2;
    float c0 = b1*y2 - b2*y1;
    float c1 = b2*y0 - b0*y2;
    float c2 = b0*y1 - b1*y0;
    const float is2 = 0.70710678f;
    float ms  = (w0*ss + w3a*dot) * 0.25f;
    float mv0 = (w1a*y0 + w2a*b0 + w4a*c0*is2) * 0.25f;
    float mv1 = (w1a*y1 + w2a*b1 + w4a*c1*is2) * 0.25f;
    float mv2 = (w1a*y2 + w2a*b2 + w4a*c2*is2) * 0.25f;
    atomicAdd(&g_agg_s[rc*64 + g], ms);
    atomicAdd(&g_agg_v[0*NF + rc*64 + g], mv0);
    atomicAdd(&g_agg_v[1*NF + rc*64 + g], mv1);
    atomicAdd(&g_agg_v[2*NF + rc*64 + g], mv2);
}

// ---------------- kernel C: node_post, 512 thr (8 groups), 2 blocks/SM ----------------
#define POST_SMEM_FLOATS (4*4096 + 8*576)
__global__ void __launch_bounds__(512)
node_post(const float* __restrict__ Wds,
          const float* __restrict__ Wdv,
          const float* __restrict__ Wsc,
          const float* __restrict__ Wps,
          const float* __restrict__ Wpv,
          const float* __restrict__ Wout,
          const int*   __restrict__ species,
          float* __restrict__ out) {
    extern __shared__ float sm[];
    float* sWds = sm;
    float* sWdv = sm + 4096;
    float* sWps = sm + 8192;
    float* sWpv = sm + 12288;
    float* buf  = sm + 16384;
    int tid = threadIdx.x;
    for (int i = tid; i < 4096; i += 512) {
        sWds[i] = Wds[i]; sWdv[i] = Wdv[i]; sWps[i] = Wps[i]; sWpv[i] = Wpv[i];
    }
    __syncthreads();
    int g = tid & 63, grp = tid >> 6, bar = grp + 1;
    float* ags = buf + grp * 576;
    float* agv = ags + 64;
    float* so  = agv + 192;
    float* vo  = so + 64;
    float* red = vo + 192;
    int group_id = blockIdx.x * 8 + grp;
    int totalGroups = gridDim.x * 8;
    for (int n = group_id; n < NN; n += totalGroups) {
        ags[g]       = g_agg_s[n*64 + g];
        agv[g]       = g_agg_v[0*NF + n*64 + g];
        agv[64 + g]  = g_agg_v[1*NF + n*64 + g];
        agv[128 + g] = g_agg_v[2*NF + n*64 + g];
        asm volatile("bar.sync %0, 64;" :: "r"(bar) : "memory");

        float sd = 0.f, vd0 = 0.f, vd1 = 0.f, vd2 = 0.f;
        #pragma unroll 8
        for (int f = 0; f < 64; f++) {
            float a  = ags[f];
            float a0 = agv[f], a1 = agv[64 + f], a2 = agv[128 + f];
            float w1 = sWds[f*64 + g], w2 = sWdv[f*64 + g];
            sd += a * w1; vd0 += a0 * w2; vd1 += a1 * w2; vd2 += a2 * w2;
        }
        sd *= 0.125f; vd0 *= 0.125f; vd1 *= 0.125f; vd2 *= 0.125f;

        int z = species[n];
        const float* wz = Wsc + z * (PSC*64) + g;
        float q0 = __ldg(wz),       q1 = __ldg(wz + 64),  q2 = __ldg(wz + 128);
        float q3 = __ldg(wz + 192), q4 = __ldg(wz + 256), q5 = __ldg(wz + 320);
        float q6 = __ldg(wz + 384), q7 = __ldg(wz + 448), q8 = __ldg(wz + 512);
        float vn2 = vd0*vd0 + vd1*vd1 + vd2*vd2;
        float s2  = sd * sd;
        float sout = q0*sd + q1*s2 + q2*vn2 + q3*s2*sd + q4*sd*vn2;
        float gv   = q5 + q6*sd + q7*s2 + q8*vn2;
        so[g] = sout;
        vo[g] = gv*vd0; vo[64 + g] = gv*vd1; vo[128 + g] = gv*vd2;
        asm volatile("bar.sync %0, 64;" :: "r"(bar) : "memory");

        float sp = 0.f, vp0 = 0.f, vp1 = 0.f, vp2 = 0.f;
        #pragma unroll 8
        for (int f = 0; f < 64; f++) {
            float a  = so[f];
            float a0 = vo[f], a1 = vo[64 + f], a2 = vo[128 + f];
            float w1 = sWps[f*64 + g], w2 = sWpv[f*64 + g];
            sp += a * w1; vp0 += a0 * w2; vp1 += a1 * w2; vp2 += a2 * w2;
        }
        sp  = sp  * 0.125f + g_skip_s[n*64 + g];
        vp0 = vp0 * 0.125f + g_skip_v[0*NF + n*64 + g];
        vp1 = vp1 * 0.125f + g_skip_v[1*NF + n*64 + g];
        vp2 = vp2 * 0.125f + g_skip_v[2*NF + n*64 + g];

        float* mrow = out + NN + (size_t)n * 256;
        mrow[g] = sp;
        mrow[64 + g*3]     = vp0;
        mrow[64 + g*3 + 1] = vp1;
        mrow[64 + g*3 + 2] = vp2;

        red[g] = sp * __ldg(Wout + g);
        asm volatile("bar.sync %0, 64;" :: "r"(bar) : "memory");
        if (g == 0) {
            float t2 = 0.f;
            #pragma unroll
            for (int i = 0; i < 64; i++) t2 += red[i];
            out[n] = t2 * 0.125f;
        }
        asm volatile("bar.sync %0, 64;" :: "r"(bar) : "memory");
    }
}

// ---------------- launch ----------------
extern "C" void kernel_launch(void* const* d_in, const int* in_sizes, int n_in,
                              void* d_out, int out_size) {
    const float* vectors    = (const float*)d_in[0];
    const float* node_feats = (const float*)d_in[1];
    const float* re         = (const float*)d_in[2];
    const float* Wss        = (const float*)d_in[3];
    const float* Wsv        = (const float*)d_in[4];
    const float* Wus        = (const float*)d_in[5];
    const float* Wuv        = (const float*)d_in[6];
    const float* W1         = (const float*)d_in[7];
    const float* W2         = (const float*)d_in[8];
    const float* W3         = (const float*)d_in[9];
    const float* W4         = (const float*)d_in[10];
    const float* Wds        = (const float*)d_in[11];
    const float* Wdv        = (const float*)d_in[12];
    const float* Wsc        = (const float*)d_in[13];
    const float* Wps        = (const float*)d_in[14];
    const float* Wpv        = (const float*)d_in[15];
    const float* Wout       = (const float*)d_in[16];
    const int*   species    = (const int*)d_in[17];
    const int*   senders    = (const int*)d_in[18];
    const int*   receivers  = (const int*)d_in[19];
    float* out = (float*)d_out;

    const int MLP_SMEM  = MLP_SMEM_FLOATS * 4;    // 195584 B
    const int POST_SMEM = POST_SMEM_FLOATS * 4;   // 83968 B
    cudaFuncSetAttribute(mlp_kernel, cudaFuncAttributeMaxDynamicSharedMemorySize, MLP_SMEM);
    cudaFuncSetAttribute(node_post,  cudaFuncAttributeMaxDynamicSharedMemorySize, POST_SMEM);

    zero_agg<<<2048, 256>>>();
    node_pre<<<444, 512>>>(node_feats, Wss, Wsv, Wus, Wuv, species);
    mlp_kernel<<<EE/256, 512, MLP_SMEM>>>(re, W1, W2, W3, W4);
    tp_scatter<<<EE*64/256, 256>>>(vectors, senders, receivers);
    node_post<<<296, 512, POST_SMEM>>>(Wds, Wdv, Wsc, Wps, Wpv, Wout, species, out);
}